// round 6
// baseline (speedup 1.0000x reference)
#include <cuda_runtime.h>

#define BATCH 4
#define CIN   96
#define DI    192
#define HH    128
#define WW    128
#define HWSZ  16384
#define KDIR  4
#define NCH   64          // chunks per chain
#define CHUNK 256         // positions per chunk
#define NDT   24          // d-tiles (DI/8)

// ---------------- scratch ----------------
__device__ float g_t1[(size_t)BATCH*DI*HWSZ];                 // in_proj output (B,D,HW)
__device__ float g_xft[(size_t)BATCH*HWSZ*DI];                // conv+silu, transposed (B,HW,D)
__device__ float g_xdbl[(size_t)BATCH*HWSZ*32];               // (B,HW,K*8) spatial order
__device__ float g_ys[(size_t)BATCH*HWSZ*KDIR*DI];            // (B,HW,K,D) spatial order
__device__ float g_g[(size_t)BATCH*HWSZ*DI];                  // gelu(sum_k ys) (B,HW,D)
__device__ float g_hpub[(size_t)16*NCH*DI];                   // published inclusive h per chunk
__device__ int   g_flag[(size_t)16*NCH*NDT*8];                // ready flags

// ---------------- f32x2 packed helpers ----------------
__device__ __forceinline__ unsigned long long pk2(float x, float y) {
    unsigned long long r;
    asm("mov.b64 %0, {%1, %2};" : "=l"(r) : "f"(x), "f"(y));
    return r;
}
__device__ __forceinline__ void upk2(float& lo, float& hi, unsigned long long v) {
    asm("mov.b64 {%0, %1}, %2;" : "=f"(lo), "=f"(hi) : "l"(v));
}
#define FMA2(d, a, b) asm("fma.rn.f32x2 %0, %1, %2, %0;" : "+l"(d) : "l"(a), "l"(b))

__device__ __forceinline__ void st_release(int* p, int v) {
    asm volatile("st.global.release.gpu.b32 [%0], %1;" :: "l"(p), "r"(v) : "memory");
}
__device__ __forceinline__ int ld_acquire(const int* p) {
    int v;
    asm volatile("ld.global.acquire.gpu.b32 %0, [%1];" : "=r"(v) : "l"(p) : "memory");
    return v;
}

// =====================================================================
// K0: clear chain flags (must run before k4 on every replay)
// =====================================================================
__global__ void k0_clear(void) {
    int i = blockIdx.x*256 + threadIdx.x;
    if (i < 16*NCH*NDT*8) g_flag[i] = 0;
}

// =====================================================================
// K1: in_proj, outputs split in half per block.
// grid (HW/64, 2, B), block 256.  smem ~64KB
// =====================================================================
__global__ void __launch_bounds__(256) k1_inproj(const float* __restrict__ x,
                                                 const float* __restrict__ w) {
    extern __shared__ float sm1[];
    float* sw = sm1;              // sw[c*98 + olocal]
    float* sx = sm1 + 96*98;      // sx[c*68 + t]
    int b = blockIdx.z, oh = blockIdx.y;
    int pos0 = blockIdx.x * 64;
    int tid = threadIdx.x;

    for (int i = tid; i < 96*96; i += 256)
        sw[(i % 96)*98 + (i / 96)] = w[oh*96*96 + (i/96)*96 + (i%96)];
    for (int i = tid; i < CIN*64; i += 256) {
        int c = i >> 6, t = i & 63;
        sx[c*68 + t] = x[((size_t)b*CIN + c)*HWSZ + pos0 + t];
    }
    __syncthreads();

    int tg = tid & 15, og = tid >> 4;
    int t0 = tg * 4, o0 = og * 6;
    unsigned long long acc[3][4];
    #pragma unroll
    for (int i = 0; i < 3; i++)
        #pragma unroll
        for (int j = 0; j < 4; j++) acc[i][j] = 0ull;

    for (int c = 0; c < CIN; ++c) {
        float4 xv = *(const float4*)&sx[c*68 + t0];
        unsigned long long xp[4] = {pk2(xv.x, xv.x), pk2(xv.y, xv.y),
                                    pk2(xv.z, xv.z), pk2(xv.w, xv.w)};
        const float* wrow = &sw[c*98 + o0];
        #pragma unroll
        for (int i = 0; i < 3; ++i) {
            unsigned long long wp = *(const unsigned long long*)&wrow[2*i];
            #pragma unroll
            for (int t = 0; t < 4; ++t) FMA2(acc[i][t], wp, xp[t]);
        }
    }
    #pragma unroll
    for (int i = 0; i < 3; ++i) {
        float lo[4], hi[4];
        #pragma unroll
        for (int t = 0; t < 4; ++t) upk2(lo[t], hi[t], acc[i][t]);
        size_t r0 = ((size_t)b*DI + oh*96 + o0 + 2*i)*HWSZ + pos0 + t0;
        *(float4*)&g_t1[r0]        = make_float4(lo[0], lo[1], lo[2], lo[3]);
        *(float4*)&g_t1[r0 + HWSZ] = make_float4(hi[0], hi[1], hi[2], hi[3]);
    }
}

// =====================================================================
// K2: depthwise 3x3 conv + bias + silu, writing TRANSPOSED output g_xft.
// grid (W/32, H, B), block 256.  smem ~112KB
// =====================================================================
__global__ void __launch_bounds__(256) k2_conv(const float* __restrict__ cw,
                                               const float* __restrict__ cb) {
    extern __shared__ float sm2[];
    float* s_in  = sm2;                 // [rc*193 + d], rc = r*34+c
    float* s_out = sm2 + 102*193;       // [w*193 + d]
    float* s_w9  = sm2 + 102*193 + 32*193;   // [d*9+i]
    float* s_b   = s_w9 + DI*9;              // [d]
    int b = blockIdx.z, h = blockIdx.y, w0 = blockIdx.x * 32;
    int tid = threadIdx.x;

    for (int i = tid; i < DI*9; i += 256) s_w9[i] = cw[i];
    for (int i = tid; i < DI; i += 256) s_b[i] = cb[i];
    for (int i = tid; i < 3*34*DI; i += 256) {
        int dd = i / 102, rc = i % 102;
        int r = rc / 34, c = rc % 34;
        int hh = h + r - 1, ww = w0 + c - 1;
        float v = 0.f;
        if (hh >= 0 && hh < HH && ww >= 0 && ww < WW)
            v = g_t1[((size_t)b*DI + dd)*HWSZ + hh*WW + ww];
        s_in[rc*193 + dd] = v;
    }
    __syncthreads();

    int w = tid & 31, dg = tid >> 5;
    #pragma unroll 4
    for (int dd = 0; dd < 24; ++dd) {
        int d = dg*24 + dd;
        float sum = s_b[d];
        #pragma unroll
        for (int r = 0; r < 3; ++r)
            #pragma unroll
            for (int dc = 0; dc < 3; ++dc)
                sum += s_w9[d*9 + r*3 + dc] * s_in[(r*34 + w + dc)*193 + d];
        s_out[w*193 + d] = sum / (1.f + __expf(-sum));
    }
    __syncthreads();

    for (int i = tid; i < 32*DI; i += 256) {
        int ww = i / DI, d = i % DI;
        g_xft[((size_t)b*HWSZ + h*WW + w0 + ww)*DI + d] = s_out[ww*193 + d];
    }
}

// =====================================================================
// K3: x_proj GEMM (32 outputs per token, spatial order), reads g_xft.
// grid (HW/64, B), block 256
// =====================================================================
__global__ void __launch_bounds__(256) k3_proj(const float* __restrict__ xpw) {
    extern __shared__ float sm3[];
    float* sxf = sm3;             // [d*80 + t]
    float* sw  = sm3 + DI*80;     // [d*33 + kc]
    int b = blockIdx.y, pos0 = blockIdx.x * 64, tid = threadIdx.x;

    for (int i = tid; i < DI*64; i += 256) {
        int po = i / DI, d = i % DI;
        sxf[d*80 + po] = g_xft[((size_t)b*HWSZ + pos0 + po)*DI + d];
    }
    for (int i = tid; i < 32*DI; i += 256) {
        int kc = i / DI, d = i % DI;
        sw[d*33 + kc] = xpw[i];
    }
    __syncthreads();

    int tg = tid & 15, kg = tid >> 4;
    int t0 = tg * 4, kc0 = kg * 2;
    float acc[4][2] = {{0,0},{0,0},{0,0},{0,0}};
    for (int d = 0; d < DI; ++d) {
        float4 xv = *(const float4*)&sxf[d*80 + t0];
        float w0 = sw[d*33 + kc0], w1 = sw[d*33 + kc0 + 1];
        acc[0][0] += xv.x*w0; acc[0][1] += xv.x*w1;
        acc[1][0] += xv.y*w0; acc[1][1] += xv.y*w1;
        acc[2][0] += xv.z*w0; acc[2][1] += xv.z*w1;
        acc[3][0] += xv.w*w0; acc[3][1] += xv.w*w1;
    }
    #pragma unroll
    for (int j = 0; j < 4; ++j) {
        size_t pos = (size_t)pos0 + t0 + j;
        *(float2*)&g_xdbl[((size_t)b*HWSZ + pos)*32 + kc0] = make_float2(acc[j][0], acc[j][1]);
    }
}

// =====================================================================
// K4: single-pass selective scan with decoupled chunk chaining.
// block 256 = 32 slots x 8 d; grid (24 dtiles, 64 chunks, 16 chains).
// Each warp owns one channel's cross-slot scan + chain hop.
// =====================================================================
__global__ void __launch_bounds__(256) k4_scan(const float* __restrict__ dtw,
                        const float* __restrict__ dtb,
                        const float* __restrict__ Alog,
                        const float* __restrict__ Dsv,
                        const int*   __restrict__ scan) {
    __shared__ float s_pa[32*9], s_pb[32*9], s_hs[32*9];
    int dg = blockIdx.x, chunk = blockIdx.y, chain = blockIdx.z;
    int b = chain >> 2, k = chain & 3;
    int tid = threadIdx.x;
    int dsub = tid & 7, slot = tid >> 3;
    int d = dg*8 + dsub;
    int kd = k*DI + d;
    int lane = tid & 31, wid = tid >> 5;

    float w0 = dtw[kd*6+0], w1 = dtw[kd*6+1], w2 = dtw[kd*6+2];
    float w3 = dtw[kd*6+3], w4 = dtw[kd*6+4], w5 = dtw[kd*6+5];
    float bias = dtb[kd];
    float Aval = -__expf(Alog[kd]);
    float Dval = Dsv[kd];
    const int*   sc     = scan + k*HWSZ + chunk*CHUNK;
    const float* xdbl_b = g_xdbl + (size_t)b*HWSZ*32 + k*8;
    const float* xft_b  = g_xft  + (size_t)b*HWSZ*DI + d;
    float*       ys_b   = g_ys   + (size_t)b*HWSZ*(KDIR*DI) + k*DI + d;

    int4 pA = *(const int4*)&sc[slot*8];
    int4 pB = *(const int4*)&sc[slot*8 + 4];
    int pos[8] = {pA.x, pA.y, pA.z, pA.w, pB.x, pB.y, pB.z, pB.w};
    float a[8], bu[8], Cv[8], uu[8];
    #pragma unroll
    for (int j = 0; j < 8; ++j) {
        const float4* xb = (const float4*)(xdbl_b + (size_t)pos[j]*32);
        float4 q1 = xb[0];
        float4 q2 = xb[1];
        float u = xft_b[(size_t)pos[j]*DI];
        float dt = bias + w0*q1.x + w1*q1.y + w2*q1.z + w3*q1.w + w4*q2.x + w5*q2.y;
        float delta = fmaxf(dt, 0.f) + __logf(1.f + __expf(-fabsf(dt)));
        a[j]  = __expf(delta * Aval);
        bu[j] = delta * q2.z * u;
        Cv[j] = q2.w;
        uu[j] = u;
    }
    float aP = a[0], bP = bu[0];
    #pragma unroll
    for (int j = 1; j < 8; ++j) { bP = a[j]*bP + bu[j]; aP *= a[j]; }
    s_pa[slot*9 + dsub] = aP;
    s_pb[slot*9 + dsub] = bP;
    __syncthreads();

    {   // warp `wid` owns channel d = dg*8 + wid
        float ai = s_pa[lane*9 + wid];
        float bi = s_pb[lane*9 + wid];
        #pragma unroll
        for (int off = 1; off < 32; off <<= 1) {
            float pa = __shfl_up_sync(0xffffffffu, ai, off);
            float pb = __shfl_up_sync(0xffffffffu, bi, off);
            if (lane >= off) { bi = ai*pb + bi; ai *= pa; }
        }
        float aE = __shfl_up_sync(0xffffffffu, ai, 1);
        float bE = __shfl_up_sync(0xffffffffu, bi, 1);
        if (lane == 0) { aE = 1.f; bE = 0.f; }

        // --- chain hop: get h_in from predecessor chunk ---
        float h_in = 0.f;
        if (chunk > 0) {
            int fidx = (((chain*NCH + (chunk-1))*NDT + dg) << 3) + wid;
            if (lane == 0) {
                while (ld_acquire(&g_flag[fidx]) == 0) { __nanosleep(32); }
                h_in = g_hpub[((size_t)chain*NCH + (chunk-1))*DI + dg*8 + wid];
            }
            h_in = __shfl_sync(0xffffffffu, h_in, 0);
        }
        // publish inclusive h of this chunk (lane 31 holds chunk aggregate)
        if (lane == 31) {
            g_hpub[((size_t)chain*NCH + chunk)*DI + dg*8 + wid] = ai*h_in + bi;
            __threadfence();
            int fidx = (((chain*NCH + chunk)*NDT + dg) << 3) + wid;
            st_release(&g_flag[fidx], 1);
        }
        // exclusive per-slot start state
        s_hs[lane*9 + wid] = aE*h_in + bE;
    }
    __syncthreads();

    float h = s_hs[slot*9 + dsub];
    #pragma unroll
    for (int j = 0; j < 8; ++j) {
        h = a[j]*h + bu[j];
        ys_b[(size_t)pos[j]*(KDIR*DI)] = Cv[j]*h + Dval*uu[j];
    }
}

// =====================================================================
// K5a: streaming sum over K + gelu.  grid (B*HW/4), block 192
// =====================================================================
__global__ void __launch_bounds__(192) k5a_gelu(void) {
    int tid = threadIdx.x;
    int q = tid % 48, po = tid / 48;
    size_t pg = (size_t)blockIdx.x*4 + po;
    const float4* src = (const float4*)(g_ys + pg*(KDIR*DI));
    float4 acc = src[q];
    #pragma unroll
    for (int kk = 1; kk < KDIR; ++kk) {
        float4 v = src[kk*48 + q];
        acc.x += v.x; acc.y += v.y; acc.z += v.z; acc.w += v.w;
    }
    float r[4] = {acc.x, acc.y, acc.z, acc.w};
    #pragma unroll
    for (int i = 0; i < 4; ++i) {
        float v = r[i];
        float z = 0.7978845608f * (v + 0.044715f*v*v*v);
        float t = 2.f / (1.f + __expf(-2.f*z)) - 1.f;
        r[i] = 0.5f * v * (1.f + t);
    }
    ((float4*)(g_g + pg*DI))[q] = make_float4(r[0], r[1], r[2], r[3]);
}

// =====================================================================
// K5b: out_proj GEMM, outputs split 2-way.  grid (HW/64, 2, B), block 256
// =====================================================================
__global__ void __launch_bounds__(256) k5b_out(const float* __restrict__ ow,
                                               float* __restrict__ out) {
    extern __shared__ float sm5[];
    float* sw = sm5;              // sw[d*50 + ol]
    float* sg = sm5 + DI*50;      // sg[d*68 + t]
    int b = blockIdx.z, oq = blockIdx.y;
    int pos0 = blockIdx.x * 64, tid = threadIdx.x;

    for (int i = tid; i < 48*DI; i += 256)
        sw[(i % DI)*50 + (i / DI)] = ow[oq*48*DI + i];
    int lane = tid & 31, wid = tid >> 5;
    #pragma unroll
    for (int pp = 0; pp < 8; ++pp) {
        int po = wid*8 + pp;
        const float* src = &g_g[((size_t)b*HWSZ + pos0 + po)*DI];
        #pragma unroll
        for (int i = 0; i < 6; ++i)
            sg[(lane + 32*i)*68 + po] = src[lane + 32*i];
    }
    __syncthreads();

    int tg = tid & 31, og = tid >> 5;
    int t0 = tg*2, o0 = og*6;
    unsigned long long acc[3][2];
    #pragma unroll
    for (int i = 0; i < 3; i++) { acc[i][0] = 0ull; acc[i][1] = 0ull; }

    for (int d = 0; d < DI; ++d) {
        float2 gv = *(const float2*)&sg[d*68 + t0];
        unsigned long long gp[2] = {pk2(gv.x, gv.x), pk2(gv.y, gv.y)};
        const float* wrow = &sw[d*50 + o0];
        #pragma unroll
        for (int i = 0; i < 3; ++i) {
            unsigned long long wp = *(const unsigned long long*)&wrow[2*i];
            FMA2(acc[i][0], wp, gp[0]);
            FMA2(acc[i][1], wp, gp[1]);
        }
    }
    #pragma unroll
    for (int i = 0; i < 3; ++i) {
        float lo0, hi0, lo1, hi1;
        upk2(lo0, hi0, acc[i][0]);
        upk2(lo1, hi1, acc[i][1]);
        size_t r0 = ((size_t)b*CIN + oq*48 + o0 + 2*i)*HWSZ + pos0 + t0;
        *(float2*)&out[r0]        = make_float2(lo0, lo1);
        *(float2*)&out[r0 + HWSZ] = make_float2(hi0, hi1);
    }
}

// =====================================================================
extern "C" void kernel_launch(void* const* d_in, const int* in_sizes, int n_in,
                              void* d_out, int out_size) {
    const float* x    = (const float*)d_in[0];
    const int*   scan = (const int*)d_in[1];
    const float* ipw  = (const float*)d_in[3];
    const float* cw   = (const float*)d_in[4];
    const float* cb   = (const float*)d_in[5];
    const float* xpw  = (const float*)d_in[6];
    const float* dtw  = (const float*)d_in[7];
    const float* dtb  = (const float*)d_in[8];
    const float* Alog = (const float*)d_in[9];
    const float* Dsv  = (const float*)d_in[10];
    const float* ow   = (const float*)d_in[11];
    float* out = (float*)d_out;

    const int SM1 = (96*98 + 96*68) * 4;
    const int SM2 = (102*193 + 32*193 + DI*9 + DI) * 4;
    const int SM3 = (DI*80 + DI*33) * 4;
    const int SM5 = (DI*50 + DI*68) * 4;
    cudaFuncSetAttribute(k1_inproj, cudaFuncAttributeMaxDynamicSharedMemorySize, SM1);
    cudaFuncSetAttribute(k2_conv,   cudaFuncAttributeMaxDynamicSharedMemorySize, SM2);
    cudaFuncSetAttribute(k3_proj,   cudaFuncAttributeMaxDynamicSharedMemorySize, SM3);
    cudaFuncSetAttribute(k5b_out,   cudaFuncAttributeMaxDynamicSharedMemorySize, SM5);

    k0_clear<<<(16*NCH*NDT*8 + 255)/256, 256>>>();
    dim3 g1(HWSZ/64, 2, BATCH);
    k1_inproj<<<g1, 256, SM1>>>(x, ipw);
    dim3 g2(WW/32, HH, BATCH);
    k2_conv<<<g2, 256, SM2>>>(cw, cb);
    dim3 g3(HWSZ/64, BATCH);
    k3_proj<<<g3, 256, SM3>>>(xpw);
    dim3 g4(NDT, NCH, 16);
    k4_scan<<<g4, 256>>>(dtw, dtb, Alog, Dsv, scan);
    k5a_gelu<<<BATCH*HWSZ/4, 192>>>();
    dim3 g5(HWSZ/64, 2, BATCH);
    k5b_out<<<g5, 256, SM5>>>(ow, out);
}

// round 8
// speedup vs baseline: 3.1518x; 3.1518x over previous
#include <cuda_runtime.h>

#define BATCH 4
#define CIN   96
#define DI    192
#define HH    128
#define WW    128
#define HWSZ  16384
#define KDIR  4

// ---------------- scratch ----------------
__device__ float g_t1[(size_t)BATCH*DI*HWSZ];                 // in_proj output (B,D,HW)
__device__ float g_xft[(size_t)BATCH*HWSZ*DI];                // conv+silu, transposed (B,HW,D)
__device__ float g_xdbl[(size_t)BATCH*HWSZ*32];               // (B,HW,K*8) spatial order
__device__ float g_ys[(size_t)BATCH*HWSZ*KDIR*DI];            // (B,HW,K,D) spatial order
__device__ float g_g[(size_t)BATCH*HWSZ*DI];                  // gelu(sum_k ys) (B,HW,D)

// ---------------- f32x2 packed helpers ----------------
__device__ __forceinline__ unsigned long long pk2(float x, float y) {
    unsigned long long r;
    asm("mov.b64 %0, {%1, %2};" : "=l"(r) : "f"(x), "f"(y));
    return r;
}
__device__ __forceinline__ void upk2(float& lo, float& hi, unsigned long long v) {
    asm("mov.b64 {%0, %1}, %2;" : "=f"(lo), "=f"(hi) : "l"(v));
}
#define FMA2(d, a, b) asm("fma.rn.f32x2 %0, %1, %2, %0;" : "+l"(d) : "l"(a), "l"(b))

// =====================================================================
// K1: in_proj, outputs split in half per block.
// grid (HW/64, 2, B), block 256.  smem ~64KB  (sw stride 98: even, 8B-aligned)
// =====================================================================
__global__ void __launch_bounds__(256) k1_inproj(const float* __restrict__ x,
                                                 const float* __restrict__ w) {
    extern __shared__ float sm1[];
    float* sw = sm1;              // sw[c*98 + olocal]
    float* sx = sm1 + 96*98;      // sx[c*68 + t]
    int b = blockIdx.z, oh = blockIdx.y;
    int pos0 = blockIdx.x * 64;
    int tid = threadIdx.x;

    for (int i = tid; i < 96*96; i += 256)
        sw[(i % 96)*98 + (i / 96)] = w[oh*96*96 + (i/96)*96 + (i%96)];
    for (int i = tid; i < CIN*64; i += 256) {
        int c = i >> 6, t = i & 63;
        sx[c*68 + t] = x[((size_t)b*CIN + c)*HWSZ + pos0 + t];
    }
    __syncthreads();

    int tg = tid & 15, og = tid >> 4;
    int t0 = tg * 4, o0 = og * 6;
    unsigned long long acc[3][4];
    #pragma unroll
    for (int i = 0; i < 3; i++)
        #pragma unroll
        for (int j = 0; j < 4; j++) acc[i][j] = 0ull;

    for (int c = 0; c < CIN; ++c) {
        float4 xv = *(const float4*)&sx[c*68 + t0];
        unsigned long long xp[4] = {pk2(xv.x, xv.x), pk2(xv.y, xv.y),
                                    pk2(xv.z, xv.z), pk2(xv.w, xv.w)};
        const float* wrow = &sw[c*98 + o0];
        #pragma unroll
        for (int i = 0; i < 3; ++i) {
            unsigned long long wp = *(const unsigned long long*)&wrow[2*i];
            #pragma unroll
            for (int t = 0; t < 4; ++t) FMA2(acc[i][t], wp, xp[t]);
        }
    }
    #pragma unroll
    for (int i = 0; i < 3; ++i) {
        float lo[4], hi[4];
        #pragma unroll
        for (int t = 0; t < 4; ++t) upk2(lo[t], hi[t], acc[i][t]);
        size_t r0 = ((size_t)b*DI + oh*96 + o0 + 2*i)*HWSZ + pos0 + t0;
        *(float4*)&g_t1[r0]        = make_float4(lo[0], lo[1], lo[2], lo[3]);
        *(float4*)&g_t1[r0 + HWSZ] = make_float4(hi[0], hi[1], hi[2], hi[3]);
    }
}

// =====================================================================
// K2: depthwise 3x3 conv + bias + silu, writing TRANSPOSED output g_xft.
// grid (W/32, H, B), block 256.  smem ~112KB
// =====================================================================
__global__ void __launch_bounds__(256) k2_conv(const float* __restrict__ cw,
                                               const float* __restrict__ cb) {
    extern __shared__ float sm2[];
    float* s_in  = sm2;                 // [rc*193 + d], rc = r*34+c
    float* s_out = sm2 + 102*193;       // [w*193 + d]
    float* s_w9  = sm2 + 102*193 + 32*193;   // [d*9+i]
    float* s_b   = s_w9 + DI*9;              // [d]
    int b = blockIdx.z, h = blockIdx.y, w0 = blockIdx.x * 32;
    int tid = threadIdx.x;

    for (int i = tid; i < DI*9; i += 256) s_w9[i] = cw[i];
    for (int i = tid; i < DI; i += 256) s_b[i] = cb[i];
    for (int i = tid; i < 3*34*DI; i += 256) {
        int dd = i / 102, rc = i % 102;
        int r = rc / 34, c = rc % 34;
        int hh = h + r - 1, ww = w0 + c - 1;
        float v = 0.f;
        if (hh >= 0 && hh < HH && ww >= 0 && ww < WW)
            v = g_t1[((size_t)b*DI + dd)*HWSZ + hh*WW + ww];
        s_in[rc*193 + dd] = v;
    }
    __syncthreads();

    int w = tid & 31, dg = tid >> 5;
    #pragma unroll 4
    for (int dd = 0; dd < 24; ++dd) {
        int d = dg*24 + dd;
        float sum = s_b[d];
        #pragma unroll
        for (int r = 0; r < 3; ++r)
            #pragma unroll
            for (int dc = 0; dc < 3; ++dc)
                sum += s_w9[d*9 + r*3 + dc] * s_in[(r*34 + w + dc)*193 + d];
        s_out[w*193 + d] = sum / (1.f + __expf(-sum));
    }
    __syncthreads();

    for (int i = tid; i < 32*DI; i += 256) {
        int ww = i / DI, d = i % DI;
        g_xft[((size_t)b*HWSZ + h*WW + w0 + ww)*DI + d] = s_out[ww*193 + d];
    }
}

// =====================================================================
// K3: x_proj GEMM (32 outputs per token, spatial order), reads g_xft.
// grid (HW/64, B), block 256.  sxf stride 84 (float4-aligned, 4-way max).
// =====================================================================
__global__ void __launch_bounds__(256) k3_proj(const float* __restrict__ xpw) {
    extern __shared__ float sm3[];
    float* sxf = sm3;             // [d*84 + t]
    float* sw  = sm3 + DI*84;     // [d*33 + kc]
    int b = blockIdx.y, pos0 = blockIdx.x * 64, tid = threadIdx.x;

    for (int i = tid; i < DI*64; i += 256) {
        int po = i / DI, d = i % DI;    // consecutive d: coalesced gmem read
        sxf[d*84 + po] = g_xft[((size_t)b*HWSZ + pos0 + po)*DI + d];
    }
    for (int i = tid; i < 32*DI; i += 256) {
        int kc = i / DI, d = i % DI;
        sw[d*33 + kc] = xpw[i];
    }
    __syncthreads();

    int tg = tid & 15, kg = tid >> 4;
    int t0 = tg * 4, kc0 = kg * 2;
    float acc[4][2] = {{0,0},{0,0},{0,0},{0,0}};
    for (int d = 0; d < DI; ++d) {
        float4 xv = *(const float4*)&sxf[d*84 + t0];
        float w0 = sw[d*33 + kc0], w1 = sw[d*33 + kc0 + 1];
        acc[0][0] += xv.x*w0; acc[0][1] += xv.x*w1;
        acc[1][0] += xv.y*w0; acc[1][1] += xv.y*w1;
        acc[2][0] += xv.z*w0; acc[2][1] += xv.z*w1;
        acc[3][0] += xv.w*w0; acc[3][1] += xv.w*w1;
    }
    #pragma unroll
    for (int j = 0; j < 4; ++j) {
        size_t pos = (size_t)pos0 + t0 + j;
        *(float2*)&g_xdbl[((size_t)b*HWSZ + pos)*32 + kc0] = make_float2(acc[j][0], acc[j][1]);
    }
}

// =====================================================================
// K4: selective scan (R2 version — best measured).
// block 256 = 32 slots x 8 d; warp w scans channel d=w via shfl.
// grid (DI/8=24, K, B) = 384 blocks.
// =====================================================================
__global__ void __launch_bounds__(256, 4) k4_scan(const float* __restrict__ dtw,
                        const float* __restrict__ dtb,
                        const float* __restrict__ Alog,
                        const float* __restrict__ Dsv,
                        const int*   __restrict__ scan) {
    __shared__ float s_pa[32*9], s_pb[32*9], s_hs[32*9];
    int b = blockIdx.z, k = blockIdx.y, dg = blockIdx.x;
    int tid = threadIdx.x;
    int dsub = tid & 7, slot = tid >> 3;
    int d = dg*8 + dsub;
    int kd = k*DI + d;
    int lane = tid & 31, wid = tid >> 5;   // 8 warps; warp w scans d=dg*8+w

    float w0 = dtw[kd*6+0], w1 = dtw[kd*6+1], w2 = dtw[kd*6+2];
    float w3 = dtw[kd*6+3], w4 = dtw[kd*6+4], w5 = dtw[kd*6+5];
    float bias = dtb[kd];
    float Aval = -__expf(Alog[kd]);
    float Dval = Dsv[kd];
    const int*   sc     = scan + k*HWSZ;
    const float* xdbl_b = g_xdbl + (size_t)b*HWSZ*32 + k*8;
    const float* xft_b  = g_xft  + (size_t)b*HWSZ*DI + d;
    float*       ys_b   = g_ys   + (size_t)b*HWSZ*(KDIR*DI) + k*DI + d;
    float hprev = 0.f;

    for (int ch = 0; ch < 64; ++ch) {
        int l0 = ch*256 + slot*8;
        int pos[8];
        #pragma unroll
        for (int j = 0; j < 8; ++j) pos[j] = sc[l0 + j];

        float a[8], bu[8], Cv[8], du[8];
        #pragma unroll
        for (int j = 0; j < 8; ++j) {
            const float4* xb = (const float4*)(xdbl_b + (size_t)pos[j]*32);
            float4 q1 = xb[0];
            float4 q2 = xb[1];
            float u = xft_b[(size_t)pos[j]*DI];
            float dt = bias + w0*q1.x + w1*q1.y + w2*q1.z + w3*q1.w + w4*q2.x + w5*q2.y;
            float delta = fmaxf(dt, 0.f) + __logf(1.f + __expf(-fabsf(dt)));
            a[j]  = __expf(delta * Aval);
            bu[j] = delta * q2.z * u;
            Cv[j] = q2.w;
            du[j] = Dval * u;
        }
        float aP = a[0], bP = bu[0];
        #pragma unroll
        for (int j = 1; j < 8; ++j) { bP = a[j]*bP + bu[j]; aP *= a[j]; }
        s_pa[slot*9 + dsub] = aP;
        s_pb[slot*9 + dsub] = bP;
        __syncthreads();

        {   // warp `wid` scans the 32 slot-partials of channel dsub==wid
            float ai = s_pa[lane*9 + wid];
            float bi = s_pb[lane*9 + wid];
            #pragma unroll
            for (int off = 1; off < 32; off <<= 1) {
                float pa = __shfl_up_sync(0xffffffffu, ai, off);
                float pb = __shfl_up_sync(0xffffffffu, bi, off);
                if (lane >= off) { bi = ai*pb + bi; ai *= pa; }
            }
            float aE = __shfl_up_sync(0xffffffffu, ai, 1);
            float bE = __shfl_up_sync(0xffffffffu, bi, 1);
            if (lane == 0) { aE = 1.f; bE = 0.f; }
            s_hs[lane*9 + wid] = aE*hprev + bE;
            float aI = __shfl_sync(0xffffffffu, ai, 31);
            float bI = __shfl_sync(0xffffffffu, bi, 31);
            hprev = aI*hprev + bI;
        }
        __syncthreads();

        float h = s_hs[slot*9 + dsub];
        #pragma unroll
        for (int j = 0; j < 8; ++j) {
            h = a[j]*h + bu[j];
            ys_b[(size_t)pos[j]*(KDIR*DI)] = Cv[j]*h + du[j];
        }
    }
}

// =====================================================================
// K5a: streaming sum over K + gelu.  grid (B*HW/4), block 192
// =====================================================================
__global__ void __launch_bounds__(192) k5a_gelu(void) {
    int tid = threadIdx.x;
    int q = tid % 48, po = tid / 48;
    size_t pg = (size_t)blockIdx.x*4 + po;
    const float4* src = (const float4*)(g_ys + pg*(KDIR*DI));
    float4 acc = src[q];
    #pragma unroll
    for (int kk = 1; kk < KDIR; ++kk) {
        float4 v = src[kk*48 + q];
        acc.x += v.x; acc.y += v.y; acc.z += v.z; acc.w += v.w;
    }
    float r[4] = {acc.x, acc.y, acc.z, acc.w};
    #pragma unroll
    for (int i = 0; i < 4; ++i) {
        float v = r[i];
        float z = 0.7978845608f * (v + 0.044715f*v*v*v);
        float t = 2.f / (1.f + __expf(-2.f*z)) - 1.f;
        r[i] = 0.5f * v * (1.f + t);
    }
    ((float4*)(g_g + pg*DI))[q] = make_float4(r[0], r[1], r[2], r[3]);
}

// =====================================================================
// K5b: out_proj GEMM, outputs split 2-way.  grid (HW/64, 2, B), block 256
// sw stride 50 (even, 8B-aligned), sg stride 70 (even, float2-aligned).
// =====================================================================
__global__ void __launch_bounds__(256) k5b_out(const float* __restrict__ ow,
                                               float* __restrict__ out) {
    extern __shared__ float sm5[];
    float* sw = sm5;              // sw[d*50 + ol]
    float* sg = sm5 + DI*50;      // sg[d*70 + t]
    int b = blockIdx.z, oq = blockIdx.y;
    int pos0 = blockIdx.x * 64, tid = threadIdx.x;

    for (int i = tid; i < 48*DI; i += 256)
        sw[(i % DI)*50 + (i / DI)] = ow[oq*48*DI + i];
    int lane = tid & 31, wid = tid >> 5;
    #pragma unroll
    for (int pp = 0; pp < 8; ++pp) {
        int po = wid*8 + pp;
        const float* src = &g_g[((size_t)b*HWSZ + pos0 + po)*DI];
        #pragma unroll
        for (int i = 0; i < 6; ++i)
            sg[(lane + 32*i)*70 + po] = src[lane + 32*i];
    }
    __syncthreads();

    int tg = tid & 31, og = tid >> 5;
    int t0 = tg*2, o0 = og*6;
    unsigned long long acc[3][2];
    #pragma unroll
    for (int i = 0; i < 3; i++) { acc[i][0] = 0ull; acc[i][1] = 0ull; }

    for (int d = 0; d < DI; ++d) {
        float2 gv = *(const float2*)&sg[d*70 + t0];
        unsigned long long gp[2] = {pk2(gv.x, gv.x), pk2(gv.y, gv.y)};
        const float* wrow = &sw[d*50 + o0];
        #pragma unroll
        for (int i = 0; i < 3; ++i) {
            unsigned long long wp = *(const unsigned long long*)&wrow[2*i];
            FMA2(acc[i][0], wp, gp[0]);
            FMA2(acc[i][1], wp, gp[1]);
        }
    }
    #pragma unroll
    for (int i = 0; i < 3; ++i) {
        float lo0, hi0, lo1, hi1;
        upk2(lo0, hi0, acc[i][0]);
        upk2(lo1, hi1, acc[i][1]);
        size_t r0 = ((size_t)b*CIN + oq*48 + o0 + 2*i)*HWSZ + pos0 + t0;
        *(float2*)&out[r0]        = make_float2(lo0, lo1);
        *(float2*)&out[r0 + HWSZ] = make_float2(hi0, hi1);
    }
}

// =====================================================================
extern "C" void kernel_launch(void* const* d_in, const int* in_sizes, int n_in,
                              void* d_out, int out_size) {
    const float* x    = (const float*)d_in[0];
    const int*   scan = (const int*)d_in[1];
    const float* ipw  = (const float*)d_in[3];
    const float* cw   = (const float*)d_in[4];
    const float* cb   = (const float*)d_in[5];
    const float* xpw  = (const float*)d_in[6];
    const float* dtw  = (const float*)d_in[7];
    const float* dtb  = (const float*)d_in[8];
    const float* Alog = (const float*)d_in[9];
    const float* Dsv  = (const float*)d_in[10];
    const float* ow   = (const float*)d_in[11];
    float* out = (float*)d_out;

    const int SM1 = (96*98 + 96*68) * 4;
    const int SM2 = (102*193 + 32*193 + DI*9 + DI) * 4;
    const int SM3 = (DI*84 + DI*33) * 4;
    const int SM5 = (DI*50 + DI*70) * 4;
    cudaFuncSetAttribute(k1_inproj, cudaFuncAttributeMaxDynamicSharedMemorySize, SM1);
    cudaFuncSetAttribute(k2_conv,   cudaFuncAttributeMaxDynamicSharedMemorySize, SM2);
    cudaFuncSetAttribute(k3_proj,   cudaFuncAttributeMaxDynamicSharedMemorySize, SM3);
    cudaFuncSetAttribute(k5b_out,   cudaFuncAttributeMaxDynamicSharedMemorySize, SM5);

    dim3 g1(HWSZ/64, 2, BATCH);
    k1_inproj<<<g1, 256, SM1>>>(x, ipw);
    dim3 g2(WW/32, HH, BATCH);
    k2_conv<<<g2, 256, SM2>>>(cw, cb);
    dim3 g3(HWSZ/64, BATCH);
    k3_proj<<<g3, 256, SM3>>>(xpw);
    dim3 g4(DI/8, KDIR, BATCH);
    k4_scan<<<g4, 256>>>(dtw, dtb, Alog, Dsv, scan);
    k5a_gelu<<<BATCH*HWSZ/4, 192>>>();
    dim3 g5(HWSZ/64, 2, BATCH);
    k5b_out<<<g5, 256, SM5>>>(ow, out);
}

// round 9
// speedup vs baseline: 3.2715x; 1.0380x over previous
#include <cuda_runtime.h>
#include <cuda_fp16.h>

#define BATCH 4
#define CIN   96
#define DI    192
#define HH    128
#define WW    128
#define HWSZ  16384
#define KDIR  4

// ---------------- scratch ----------------
__device__ float  g_t1[(size_t)BATCH*DI*HWSZ];                // in_proj output (B,D,HW)
__device__ float  g_xft[(size_t)BATCH*HWSZ*DI];               // conv+silu, transposed (B,HW,D)
__device__ float  g_xdbl[(size_t)BATCH*HWSZ*32];              // (B,HW,K*8) spatial order
__device__ __half g_ys[(size_t)BATCH*HWSZ*KDIR*DI];           // (B,HW,K,D) spatial order, fp16
__device__ float  g_g[(size_t)BATCH*HWSZ*DI];                 // gelu(sum_k ys) (B,HW,D)

// ---------------- f32x2 packed helpers ----------------
__device__ __forceinline__ unsigned long long pk2(float x, float y) {
    unsigned long long r;
    asm("mov.b64 %0, {%1, %2};" : "=l"(r) : "f"(x), "f"(y));
    return r;
}
__device__ __forceinline__ void upk2(float& lo, float& hi, unsigned long long v) {
    asm("mov.b64 {%0, %1}, %2;" : "=f"(lo), "=f"(hi) : "l"(v));
}
#define FMA2(d, a, b) asm("fma.rn.f32x2 %0, %1, %2, %0;" : "+l"(d) : "l"(a), "l"(b))

// =====================================================================
// K1: in_proj, outputs split in half per block.
// grid (HW/64, 2, B), block 256.  smem ~64KB
// =====================================================================
__global__ void __launch_bounds__(256) k1_inproj(const float* __restrict__ x,
                                                 const float* __restrict__ w) {
    extern __shared__ float sm1[];
    float* sw = sm1;              // sw[c*98 + olocal]
    float* sx = sm1 + 96*98;      // sx[c*68 + t]
    int b = blockIdx.z, oh = blockIdx.y;
    int pos0 = blockIdx.x * 64;
    int tid = threadIdx.x;

    for (int i = tid; i < 96*96; i += 256)
        sw[(i % 96)*98 + (i / 96)] = w[oh*96*96 + (i/96)*96 + (i%96)];
    for (int i = tid; i < CIN*64; i += 256) {
        int c = i >> 6, t = i & 63;
        sx[c*68 + t] = x[((size_t)b*CIN + c)*HWSZ + pos0 + t];
    }
    __syncthreads();

    int tg = tid & 15, og = tid >> 4;
    int t0 = tg * 4, o0 = og * 6;
    unsigned long long acc[3][4];
    #pragma unroll
    for (int i = 0; i < 3; i++)
        #pragma unroll
        for (int j = 0; j < 4; j++) acc[i][j] = 0ull;

    for (int c = 0; c < CIN; ++c) {
        float4 xv = *(const float4*)&sx[c*68 + t0];
        unsigned long long xp[4] = {pk2(xv.x, xv.x), pk2(xv.y, xv.y),
                                    pk2(xv.z, xv.z), pk2(xv.w, xv.w)};
        const float* wrow = &sw[c*98 + o0];
        #pragma unroll
        for (int i = 0; i < 3; ++i) {
            unsigned long long wp = *(const unsigned long long*)&wrow[2*i];
            #pragma unroll
            for (int t = 0; t < 4; ++t) FMA2(acc[i][t], wp, xp[t]);
        }
    }
    #pragma unroll
    for (int i = 0; i < 3; ++i) {
        float lo[4], hi[4];
        #pragma unroll
        for (int t = 0; t < 4; ++t) upk2(lo[t], hi[t], acc[i][t]);
        size_t r0 = ((size_t)b*DI + oh*96 + o0 + 2*i)*HWSZ + pos0 + t0;
        *(float4*)&g_t1[r0]        = make_float4(lo[0], lo[1], lo[2], lo[3]);
        *(float4*)&g_t1[r0 + HWSZ] = make_float4(hi[0], hi[1], hi[2], hi[3]);
    }
}

// =====================================================================
// K2: depthwise 3x3 conv + bias + silu, writing TRANSPOSED output g_xft.
// grid (W/32, H, B), block 256.  smem ~112KB
// =====================================================================
__global__ void __launch_bounds__(256) k2_conv(const float* __restrict__ cw,
                                               const float* __restrict__ cb) {
    extern __shared__ float sm2[];
    float* s_in  = sm2;                 // [rc*193 + d], rc = r*34+c
    float* s_out = sm2 + 102*193;       // [w*193 + d]
    float* s_w9  = sm2 + 102*193 + 32*193;   // [d*9+i]
    float* s_b   = s_w9 + DI*9;              // [d]
    int b = blockIdx.z, h = blockIdx.y, w0 = blockIdx.x * 32;
    int tid = threadIdx.x;

    for (int i = tid; i < DI*9; i += 256) s_w9[i] = cw[i];
    for (int i = tid; i < DI; i += 256) s_b[i] = cb[i];
    for (int i = tid; i < 3*34*DI; i += 256) {
        int dd = i / 102, rc = i % 102;
        int r = rc / 34, c = rc % 34;
        int hh = h + r - 1, ww = w0 + c - 1;
        float v = 0.f;
        if (hh >= 0 && hh < HH && ww >= 0 && ww < WW)
            v = g_t1[((size_t)b*DI + dd)*HWSZ + hh*WW + ww];
        s_in[rc*193 + dd] = v;
    }
    __syncthreads();

    int w = tid & 31, dg = tid >> 5;
    #pragma unroll 4
    for (int dd = 0; dd < 24; ++dd) {
        int d = dg*24 + dd;
        float sum = s_b[d];
        #pragma unroll
        for (int r = 0; r < 3; ++r)
            #pragma unroll
            for (int dc = 0; dc < 3; ++dc)
                sum += s_w9[d*9 + r*3 + dc] * s_in[(r*34 + w + dc)*193 + d];
        s_out[w*193 + d] = sum / (1.f + __expf(-sum));
    }
    __syncthreads();

    for (int i = tid; i < 32*DI; i += 256) {
        int ww = i / DI, d = i % DI;
        g_xft[((size_t)b*HWSZ + h*WW + w0 + ww)*DI + d] = s_out[ww*193 + d];
    }
}

// =====================================================================
// K3: x_proj GEMM (32 outputs per token, spatial order), reads g_xft.
// grid (HW/64, B), block 256.  sxf stride 84 (float4-aligned, 4-way max).
// =====================================================================
__global__ void __launch_bounds__(256) k3_proj(const float* __restrict__ xpw) {
    extern __shared__ float sm3[];
    float* sxf = sm3;             // [d*84 + t]
    float* sw  = sm3 + DI*84;     // [d*33 + kc]
    int b = blockIdx.y, pos0 = blockIdx.x * 64, tid = threadIdx.x;

    for (int i = tid; i < DI*64; i += 256) {
        int po = i / DI, d = i % DI;
        sxf[d*84 + po] = g_xft[((size_t)b*HWSZ + pos0 + po)*DI + d];
    }
    for (int i = tid; i < 32*DI; i += 256) {
        int kc = i / DI, d = i % DI;
        sw[d*33 + kc] = xpw[i];
    }
    __syncthreads();

    int tg = tid & 15, kg = tid >> 4;
    int t0 = tg * 4, kc0 = kg * 2;
    float acc[4][2] = {{0,0},{0,0},{0,0},{0,0}};
    for (int d = 0; d < DI; ++d) {
        float4 xv = *(const float4*)&sxf[d*84 + t0];
        float w0 = sw[d*33 + kc0], w1 = sw[d*33 + kc0 + 1];
        acc[0][0] += xv.x*w0; acc[0][1] += xv.x*w1;
        acc[1][0] += xv.y*w0; acc[1][1] += xv.y*w1;
        acc[2][0] += xv.z*w0; acc[2][1] += xv.z*w1;
        acc[3][0] += xv.w*w0; acc[3][1] += xv.w*w1;
    }
    #pragma unroll
    for (int j = 0; j < 4; ++j) {
        size_t pos = (size_t)pos0 + t0 + j;
        *(float2*)&g_xdbl[((size_t)b*HWSZ + pos)*32 + kc0] = make_float2(acc[j][0], acc[j][1]);
    }
}

// =====================================================================
// K4: selective scan.  block 256 = 32 slots x 8 d; warp w scans channel d=w.
// grid (DI/8=24, K, B) = 384 blocks.  ys stored fp16.
// =====================================================================
__global__ void __launch_bounds__(256, 4) k4_scan(const float* __restrict__ dtw,
                        const float* __restrict__ dtb,
                        const float* __restrict__ Alog,
                        const float* __restrict__ Dsv,
                        const int*   __restrict__ scan) {
    __shared__ float s_pa[32*9], s_pb[32*9], s_hs[32*9];
    int b = blockIdx.z, k = blockIdx.y, dg = blockIdx.x;
    int tid = threadIdx.x;
    int dsub = tid & 7, slot = tid >> 3;
    int d = dg*8 + dsub;
    int kd = k*DI + d;
    int lane = tid & 31, wid = tid >> 5;   // 8 warps; warp w scans d=dg*8+w

    float w0 = dtw[kd*6+0], w1 = dtw[kd*6+1], w2 = dtw[kd*6+2];
    float w3 = dtw[kd*6+3], w4 = dtw[kd*6+4], w5 = dtw[kd*6+5];
    float bias = dtb[kd];
    float Aval = -__expf(Alog[kd]);
    float Dval = Dsv[kd];
    const int*   sc     = scan + k*HWSZ;
    const float* xdbl_b = g_xdbl + (size_t)b*HWSZ*32 + k*8;
    const float* xft_b  = g_xft  + (size_t)b*HWSZ*DI + d;
    __half*      ys_b   = g_ys   + (size_t)b*HWSZ*(KDIR*DI) + k*DI + d;
    float hprev = 0.f;

    for (int ch = 0; ch < 64; ++ch) {
        int l0 = ch*256 + slot*8;
        int4 pA = *(const int4*)&sc[l0];
        int4 pB = *(const int4*)&sc[l0 + 4];
        int pos[8] = {pA.x, pA.y, pA.z, pA.w, pB.x, pB.y, pB.z, pB.w};

        float a[8], bu[8], Cv[8], du[8];
        #pragma unroll
        for (int j = 0; j < 8; ++j) {
            const float4* xb = (const float4*)(xdbl_b + (size_t)pos[j]*32);
            float4 q1 = xb[0];
            float4 q2 = xb[1];
            float u = xft_b[(size_t)pos[j]*DI];
            float dt = bias + w0*q1.x + w1*q1.y + w2*q1.z + w3*q1.w + w4*q2.x + w5*q2.y;
            float delta = fmaxf(dt, 0.f) + __logf(1.f + __expf(-fabsf(dt)));
            a[j]  = __expf(delta * Aval);
            bu[j] = delta * q2.z * u;
            Cv[j] = q2.w;
            du[j] = Dval * u;
        }
        float aP = a[0], bP = bu[0];
        #pragma unroll
        for (int j = 1; j < 8; ++j) { bP = a[j]*bP + bu[j]; aP *= a[j]; }
        s_pa[slot*9 + dsub] = aP;
        s_pb[slot*9 + dsub] = bP;
        __syncthreads();

        {   // warp `wid` scans the 32 slot-partials of channel dsub==wid
            float ai = s_pa[lane*9 + wid];
            float bi = s_pb[lane*9 + wid];
            #pragma unroll
            for (int off = 1; off < 32; off <<= 1) {
                float pa = __shfl_up_sync(0xffffffffu, ai, off);
                float pb = __shfl_up_sync(0xffffffffu, bi, off);
                if (lane >= off) { bi = ai*pb + bi; ai *= pa; }
            }
            float aE = __shfl_up_sync(0xffffffffu, ai, 1);
            float bE = __shfl_up_sync(0xffffffffu, bi, 1);
            if (lane == 0) { aE = 1.f; bE = 0.f; }
            s_hs[lane*9 + wid] = aE*hprev + bE;
            float aI = __shfl_sync(0xffffffffu, ai, 31);
            float bI = __shfl_sync(0xffffffffu, bi, 31);
            hprev = aI*hprev + bI;
        }
        __syncthreads();

        float h = s_hs[slot*9 + dsub];
        #pragma unroll
        for (int j = 0; j < 8; ++j) {
            h = a[j]*h + bu[j];
            ys_b[(size_t)pos[j]*(KDIR*DI)] = __float2half_rn(Cv[j]*h + du[j]);
        }
    }
}

// =====================================================================
// K5a: streaming sum over K (fp16 ys) + gelu.  grid (B*HW/4), block 192
// thread q of 48 handles 4 d (2 half2) per position.
// =====================================================================
__global__ void __launch_bounds__(192) k5a_gelu(void) {
    int tid = threadIdx.x;
    int q = tid % 48, po = tid / 48;
    size_t pg = (size_t)blockIdx.x*4 + po;
    const __half2* src = (const __half2*)(g_ys + pg*(KDIR*DI));
    float2 a0 = __half22float2(src[2*q]);
    float2 a1 = __half22float2(src[2*q + 1]);
    #pragma unroll
    for (int kk = 1; kk < KDIR; ++kk) {
        float2 v0 = __half22float2(src[kk*96 + 2*q]);
        float2 v1 = __half22float2(src[kk*96 + 2*q + 1]);
        a0.x += v0.x; a0.y += v0.y; a1.x += v1.x; a1.y += v1.y;
    }
    float r[4] = {a0.x, a0.y, a1.x, a1.y};
    #pragma unroll
    for (int i = 0; i < 4; ++i) {
        float v = r[i];
        float z = 0.7978845608f * (v + 0.044715f*v*v*v);
        float t = 2.f / (1.f + __expf(-2.f*z)) - 1.f;
        r[i] = 0.5f * v * (1.f + t);
    }
    ((float4*)(g_g + pg*DI))[q] = make_float4(r[0], r[1], r[2], r[3]);
}

// =====================================================================
// K5b: out_proj GEMM, outputs split 2-way.  grid (HW/64, 2, B), block 256
// =====================================================================
__global__ void __launch_bounds__(256) k5b_out(const float* __restrict__ ow,
                                               float* __restrict__ out) {
    extern __shared__ float sm5[];
    float* sw = sm5;              // sw[d*50 + ol]
    float* sg = sm5 + DI*50;      // sg[d*70 + t]
    int b = blockIdx.z, oq = blockIdx.y;
    int pos0 = blockIdx.x * 64, tid = threadIdx.x;

    for (int i = tid; i < 48*DI; i += 256)
        sw[(i % DI)*50 + (i / DI)] = ow[oq*48*DI + i];
    int lane = tid & 31, wid = tid >> 5;
    #pragma unroll
    for (int pp = 0; pp < 8; ++pp) {
        int po = wid*8 + pp;
        const float* src = &g_g[((size_t)b*HWSZ + pos0 + po)*DI];
        #pragma unroll
        for (int i = 0; i < 6; ++i)
            sg[(lane + 32*i)*70 + po] = src[lane + 32*i];
    }
    __syncthreads();

    int tg = tid & 31, og = tid >> 5;
    int t0 = tg*2, o0 = og*6;
    unsigned long long acc[3][2];
    #pragma unroll
    for (int i = 0; i < 3; i++) { acc[i][0] = 0ull; acc[i][1] = 0ull; }

    for (int d = 0; d < DI; ++d) {
        float2 gv = *(const float2*)&sg[d*70 + t0];
        unsigned long long gp[2] = {pk2(gv.x, gv.x), pk2(gv.y, gv.y)};
        const float* wrow = &sw[d*50 + o0];
        #pragma unroll
        for (int i = 0; i < 3; ++i) {
            unsigned long long wp = *(const unsigned long long*)&wrow[2*i];
            FMA2(acc[i][0], wp, gp[0]);
            FMA2(acc[i][1], wp, gp[1]);
        }
    }
    #pragma unroll
    for (int i = 0; i < 3; ++i) {
        float lo0, hi0, lo1, hi1;
        upk2(lo0, hi0, acc[i][0]);
        upk2(lo1, hi1, acc[i][1]);
        size_t r0 = ((size_t)b*CIN + oq*48 + o0 + 2*i)*HWSZ + pos0 + t0;
        *(float2*)&out[r0]        = make_float2(lo0, lo1);
        *(float2*)&out[r0 + HWSZ] = make_float2(hi0, hi1);
    }
}

// =====================================================================
extern "C" void kernel_launch(void* const* d_in, const int* in_sizes, int n_in,
                              void* d_out, int out_size) {
    const float* x    = (const float*)d_in[0];
    const int*   scan = (const int*)d_in[1];
    const float* ipw  = (const float*)d_in[3];
    const float* cw   = (const float*)d_in[4];
    const float* cb   = (const float*)d_in[5];
    const float* xpw  = (const float*)d_in[6];
    const float* dtw  = (const float*)d_in[7];
    const float* dtb  = (const float*)d_in[8];
    const float* Alog = (const float*)d_in[9];
    const float* Dsv  = (const float*)d_in[10];
    const float* ow   = (const float*)d_in[11];
    float* out = (float*)d_out;

    const int SM1 = (96*98 + 96*68) * 4;
    const int SM2 = (102*193 + 32*193 + DI*9 + DI) * 4;
    const int SM3 = (DI*84 + DI*33) * 4;
    const int SM5 = (DI*50 + DI*70) * 4;
    cudaFuncSetAttribute(k1_inproj, cudaFuncAttributeMaxDynamicSharedMemorySize, SM1);
    cudaFuncSetAttribute(k2_conv,   cudaFuncAttributeMaxDynamicSharedMemorySize, SM2);
    cudaFuncSetAttribute(k3_proj,   cudaFuncAttributeMaxDynamicSharedMemorySize, SM3);
    cudaFuncSetAttribute(k5b_out,   cudaFuncAttributeMaxDynamicSharedMemorySize, SM5);

    dim3 g1(HWSZ/64, 2, BATCH);
    k1_inproj<<<g1, 256, SM1>>>(x, ipw);
    dim3 g2(WW/32, HH, BATCH);
    k2_conv<<<g2, 256, SM2>>>(cw, cb);
    dim3 g3(HWSZ/64, BATCH);
    k3_proj<<<g3, 256, SM3>>>(xpw);
    dim3 g4(DI/8, KDIR, BATCH);
    k4_scan<<<g4, 256>>>(dtw, dtb, Alog, Dsv, scan);
    k5a_gelu<<<BATCH*HWSZ/4, 192>>>();
    dim3 g5(HWSZ/64, 2, BATCH);
    k5b_out<<<g5, 256, SM5>>>(ow, out);
}